// round 14
// baseline (speedup 1.0000x reference)
#include <cuda_runtime.h>
#include <math.h>

#define IC 128
#define NC 5
#define DD 153
#define DP 160      // padded capsule dim
#define DDP 160     // padded d-dim for hmT
#define CD 765
#define CDP 768     // padded row stride for GEMM outputs / Wp
#define ROWP 800    // NC*DP
#define KD 768
#define NQV 256
#define EPSF 1e-8f
#define NCHUNK 3
#define DCH 51      // 3*51 = 153 = DD

__device__ __align__(16) float g_hm[IC * CDP];        // hat_m fp32 (GEMM out)
__device__ __align__(16) float g_hq[NQV * CDP];       // hat_q fp32
__device__ __align__(16) float g_hmT[NC * DDP * IC];  // [c][dpad][i] fp32
__device__ __align__(16) float g_hmP[IC * ROWP];      // [i][c][dp] fp32, pads 0
__device__ __align__(16) float g_mean[NC * IC];       // [c][i]
__device__ __align__(16) float g_norm[NC * IC];       // [c][i]
__device__ __align__(16) float g_Wp[KD * CDP];        // zero-padded W

__device__ __forceinline__ float warp_sum(float v) {
#pragma unroll
  for (int o = 16; o; o >>= 1) v += __shfl_xor_sync(0xffffffffu, v, o);
  return v;
}

// ---------------------------------------------------------------------------
// Pad W [768][765] -> Wp [768][768], float4 per thread where possible.
// Layout: idx over 147456 float4 slots of Wp (589824 floats / 4).
// A float4 at Wp offset f covers cols [f%768 .. f%768+3]; source is W row
// k=f/768 cols c..c+3 (guarded).
// ---------------------------------------------------------------------------
__global__ __launch_bounds__(256) void wpad_kernel(const float* __restrict__ W,
                                                   float* __restrict__ Wp) {
  int f4 = blockIdx.x * 256 + threadIdx.x;          // float4 index
  if (f4 >= KD * CDP / 4) return;
  int f = f4 * 4;
  int k = f / CDP, c = f - k * CDP;
  float4 v;
  const float* src = W + k * CD + c;
  v.x = (c + 0 < CD) ? src[0] : 0.f;
  v.y = (c + 1 < CD) ? src[1] : 0.f;
  v.z = (c + 2 < CD) ? src[2] : 0.f;
  v.w = (c + 3 < CD) ? src[3] : 0.f;
  *(float4*)(Wp + f) = v;
}

// ---------------------------------------------------------------------------
// GEMM: 32x32 tiles, grid (24,12)=288 blocks, 128 threads, 4x2 reg tile.
// ---------------------------------------------------------------------------
#define BM 32
#define BN 32
#define BK 32

__global__ __launch_bounds__(128) void gemm_kernel(
    const float* __restrict__ Am, const float* __restrict__ Aq,
    const float* __restrict__ Wp, const float* __restrict__ bias,
    float* __restrict__ Om, float* __restrict__ Oq) {
  __shared__ float As[BK][BM];
  __shared__ float Bs[BK][BN];
  const int t = threadIdx.x;
  const int row0 = blockIdx.y * BM;
  const int c0 = blockIdx.x * BN;

  const float* A;
  float* O;
  if (row0 < IC) { A = Am + row0 * KD; O = Om + row0 * CDP; }
  else           { A = Aq + (row0 - IC) * KD; O = Oq + (row0 - IC) * CDP; }

  const int ar = t >> 3, akc = (t & 7) << 2;
  const int br = t >> 3, bc = (t & 7) << 2;
  const int ty = t >> 4, tx = t & 15;

  float acc[4][2] = {};

  for (int k0 = 0; k0 < KD; k0 += BK) {
#pragma unroll
    for (int h = 0; h < 2; ++h) {
      float4 av = *(const float4*)(A + (ar + 16 * h) * KD + k0 + akc);
      As[akc + 0][ar + 16 * h] = av.x;
      As[akc + 1][ar + 16 * h] = av.y;
      As[akc + 2][ar + 16 * h] = av.z;
      As[akc + 3][ar + 16 * h] = av.w;
      *(float4*)&Bs[br + 16 * h][bc] =
          *(const float4*)(Wp + (k0 + br + 16 * h) * CDP + c0 + bc);
    }
    __syncthreads();
#pragma unroll
    for (int kk = 0; kk < BK; ++kk) {
      float4 a4 = *(const float4*)&As[kk][ty << 2];
      float b0 = Bs[kk][tx << 1];
      float b1 = Bs[kk][(tx << 1) + 1];
      acc[0][0] += a4.x * b0; acc[0][1] += a4.x * b1;
      acc[1][0] += a4.y * b0; acc[1][1] += a4.y * b1;
      acc[2][0] += a4.z * b0; acc[2][1] += a4.z * b1;
      acc[3][0] += a4.w * b0; acc[3][1] += a4.w * b1;
    }
    __syncthreads();
  }

#pragma unroll
  for (int rr = 0; rr < 4; ++rr) {
    int lr = (ty << 2) + rr;
#pragma unroll
    for (int j = 0; j < 2; ++j) {
      int c = c0 + (tx << 1) + j;
      if (c < CD) O[lr * CDP + c] = acc[rr][j] + bias[c];
    }
  }
}

// ---------------------------------------------------------------------------
// Prep: blocks 0..79 = stats + hmP fp32; blocks 80..179 = transpose fp32
// into d-padded hmT (zero rows for d in [153,160)).
// ---------------------------------------------------------------------------
__global__ __launch_bounds__(256) void prep_kernel(
    const float* __restrict__ hm, float* __restrict__ hmP,
    float* __restrict__ hmT, float* __restrict__ meanA,
    float* __restrict__ normA) {
  const int t = threadIdx.x;
  if (blockIdx.x < 80) {
    int g = blockIdx.x * 8 + (t >> 5);
    int lane = t & 31;
    int i = g / NC, c = g - i * NC;
    const float* row = hm + i * CDP + c * DD;
    float vals[5];
    float s = 0.f, s2 = 0.f;
#pragma unroll
    for (int k = 0; k < 5; ++k) {
      int d = lane + 32 * k;
      float x = (d < DD) ? row[d] : 0.f;
      vals[k] = x;
      s += x;
      s2 += x * x;
    }
    s = warp_sum(s);
    s2 = warp_sum(s2);
    float mean = s * (1.f / DD);
    if (lane == 0) {
      meanA[c * IC + i] = mean;
      normA[c * IC + i] = sqrtf(fmaxf(s2 - DD * mean * mean, 0.f));
    }
#pragma unroll
    for (int k = 0; k < 5; ++k) {
      int d = lane + 32 * k;
      hmP[i * ROWP + c * DP + d] = vals[k];
    }
  } else {
    __shared__ float sm[32][33];
    int bx = blockIdx.x - 80;
    int c = bx / 20;
    int rem = bx - c * 20;
    int i0 = (rem / 5) * 32;
    int d0 = (rem % 5) * 32;
    int tx = t & 31, ty = t >> 5;
#pragma unroll
    for (int k = 0; k < 4; ++k) {
      int i = i0 + ty + 8 * k;
      int d = d0 + tx;
      sm[tx][ty + 8 * k] = (d < DD) ? hm[i * CDP + c * DD + d] : 0.f;
    }
    __syncthreads();
#pragma unroll
    for (int k = 0; k < 4; ++k) {
      int d = d0 + ty + 8 * k;
      hmT[(c * DDP + d) * IC + i0 + tx] = sm[ty + 8 * k][tx];  // zeros d>=153
    }
  }
}

// ---------------------------------------------------------------------------
// Routing v14: ONE query per block, 512 threads, grid 256, 2 blocks/SM.
//   A: 15 warps (ch 0..2, c 0..4), 51 d's, 8-d load batches (MLP 8).
//   I: t<128: per-i a-update/p/softmax/dsp.
//   B: t<400: thread per (c,d2), 16-i load batches (MLP 16).
//   S: warps 0..4: squash + tq update + next norms.
// ---------------------------------------------------------------------------
#define SMF_TV 0
#define SMF_HV (SMF_TV + NC * DP * 2)
#define SMF_NUM (SMF_HV + NC * DP)
#define SMF_MDV (SMF_NUM + NCHUNK * NC * IC)
#define SMF_A (SMF_MDV + NCHUNK * NC * IC)
#define SMF_P (SMF_A + NC * IC)
#define SMF_DSP (SMF_P + NC * IC)
#define SMF_MEAN (SMF_DSP + NC * IC)
#define SMF_NORM (SMF_MEAN + NC * IC)
#define SMF_RNQ (SMF_NORM + NC * IC)
#define SMF_STQ (SMF_RNQ + NC)
#define SMF_TOTAL (SMF_STQ + NC)

__global__ __launch_bounds__(512, 2) void routing_kernel(
    const float* __restrict__ hmT, const float* __restrict__ hmP,
    const float* __restrict__ meanA, const float* __restrict__ normA,
    const float* __restrict__ hq, float* __restrict__ out) {
  extern __shared__ float smem[];
  float2* tv = (float2*)(smem + SMF_TV);  // [c*DP+d] = {tq, v}
  float* hv = smem + SMF_HV;
  float* num3 = smem + SMF_NUM;
  float* mdv3 = smem + SMF_MDV;
  float* a_s = smem + SMF_A;
  float* p_s = smem + SMF_P;
  float* dsp_s = smem + SMF_DSP;
  float* mean_s = smem + SMF_MEAN;
  float* norm_s = smem + SMF_NORM;
  float* rnq = smem + SMF_RNQ;
  float* stq = smem + SMF_STQ;

  const int q = blockIdx.x;
  const int t = threadIdx.x;
  const int w = t >> 5, lane = t & 31;

  for (int j = t; j < NC * DP; j += 512) {
    int c = j / DP, d = j - c * DP;
    float x = (d < DD) ? hq[q * CDP + c * DD + d] : 0.f;
    tv[j] = make_float2(x, 0.f);
  }
  for (int j = t; j < NC * IC; j += 512) {
    a_s[j] = 0.f;
    mean_s[j] = meanA[j];
    norm_s[j] = normA[j];
  }
  __syncthreads();

  // prologue: initial norms (warps 0..4: c=w)
  if (w < NC) {
    const int c = w;
    const float2* tvc = tv + c * DP;
    float s = 0.f, s2 = 0.f;
    for (int d = lane; d < DD; d += 32) {
      float x = tvc[d].x;
      s += x;
      s2 += x * x;
    }
    s = warp_sum(s);
    s2 = warp_sum(s2);
    if (lane == 0) {
      float mean = s * (1.f / DD);
      rnq[c] = sqrtf(fmaxf(s2 - DD * mean * mean, 0.f));
      stq[c] = s;
    }
  }
  __syncthreads();

  for (int r = 0; r < 3; ++r) {
    // ---- phase A: 15 warps (ch, c), 8-d load batches ----
    if (w < NCHUNK * NC) {
      const int c = w % NC;
      const int ch = w / NC;
      const int d0 = ch * DCH;
      const float4* base = (const float4*)hmT + (c * DDP + d0) * (IC / 4) + lane;
      const float2* tvc = tv + c * DP + d0;
      const int o = ch * (NC * IC) + c * IC + 4 * lane;
      float4 an = {0, 0, 0, 0}, av = {0, 0, 0, 0};
      if (r == 0) {
        // 48 = 6 batches of 8, remainder 3
#pragma unroll
        for (int b = 0; b < 6; ++b) {
          float4 h[8];
          float tq[8];
#pragma unroll
          for (int u = 0; u < 8; ++u) h[u] = base[(8 * b + u) * (IC / 4)];
#pragma unroll
          for (int u = 0; u < 8; ++u) tq[u] = tvc[8 * b + u].x;
#pragma unroll
          for (int u = 0; u < 8; ++u) {
            an.x += h[u].x * tq[u]; an.y += h[u].y * tq[u];
            an.z += h[u].z * tq[u]; an.w += h[u].w * tq[u];
          }
        }
#pragma unroll
        for (int d = 48; d < DCH; ++d) {
          float4 h = base[d * (IC / 4)];
          float tq = tvc[d].x;
          an.x += h.x * tq; an.y += h.y * tq; an.z += h.z * tq; an.w += h.w * tq;
        }
        *(float4*)(num3 + o) = an;
      } else {
#pragma unroll
        for (int b = 0; b < 6; ++b) {
          float4 h[8];
          float2 tq[8];
#pragma unroll
          for (int u = 0; u < 8; ++u) h[u] = base[(8 * b + u) * (IC / 4)];
#pragma unroll
          for (int u = 0; u < 8; ++u) tq[u] = tvc[8 * b + u];
#pragma unroll
          for (int u = 0; u < 8; ++u) {
            an.x += h[u].x * tq[u].x; an.y += h[u].y * tq[u].x;
            an.z += h[u].z * tq[u].x; an.w += h[u].w * tq[u].x;
            av.x += h[u].x * tq[u].y; av.y += h[u].y * tq[u].y;
            av.z += h[u].z * tq[u].y; av.w += h[u].w * tq[u].y;
          }
        }
#pragma unroll
        for (int d = 48; d < DCH; ++d) {
          float4 h = base[d * (IC / 4)];
          float2 tq = tvc[d];
          an.x += h.x * tq.x; an.y += h.y * tq.x; an.z += h.z * tq.x; an.w += h.w * tq.x;
          av.x += h.x * tq.y; av.y += h.y * tq.y; av.z += h.z * tq.y; av.w += h.w * tq.y;
        }
        *(float4*)(num3 + o) = an;
        *(float4*)(mdv3 + o) = av;
      }
    }
    __syncthreads();

    // ---- phase I: t < 128 ----
    if (t < IC) {
      const int i = t;
      float p[NC];
      if (r == 0) {
#pragma unroll
        for (int c = 0; c < NC; ++c) {
          int o = c * IC + i;
          float num = num3[o] + num3[NC * IC + o] + num3[2 * NC * IC + o];
          num -= mean_s[o] * stq[c];
          float den = norm_s[o] * rnq[c] + EPSF;
          float x = __fdividef(num, den);
          float e2 = __expf(2.f * x);
          p[c] = __fdividef(e2 - 1.f, e2 + 1.f);
          p_s[o] = p[c];
          dsp_s[o] = 0.2f + p[c];
        }
      } else {
        float a[NC];
        float amax = -1e30f;
#pragma unroll
        for (int c = 0; c < NC; ++c) {
          int o = c * IC + i;
          float num = num3[o] + num3[NC * IC + o] + num3[2 * NC * IC + o];
          float mdv = mdv3[o] + mdv3[NC * IC + o] + mdv3[2 * NC * IC + o];
          num -= mean_s[o] * stq[c];
          float po = p_s[o];
          float av = a_s[o] + po * mdv;
          a_s[o] = av;
          a[c] = av;
          float den = norm_s[o] * rnq[c] + EPSF;
          float x = __fdividef(num, den);
          float e2 = __expf(2.f * x);
          p[c] = __fdividef(e2 - 1.f, e2 + 1.f);
          p_s[o] = p[c];
          amax = fmaxf(amax, av);
        }
        float es = 0.f, e[NC];
#pragma unroll
        for (int c = 0; c < NC; ++c) {
          e[c] = __expf(a[c] - amax);
          es += e[c];
        }
        float inv = __fdividef(1.f, es);
#pragma unroll
        for (int c = 0; c < NC; ++c) dsp_s[c * IC + i] = e[c] * inv + p[c];
      }
    }
    __syncthreads();

    // ---- phase B: t < 400, thread per (c,d2), 16-i load batches ----
    if (t < NC * (DP / 2)) {
      const int c = t / (DP / 2);
      const int d2 = t - c * (DP / 2);
      const float2* hp = (const float2*)hmP + c * (DP / 2) + d2;
      const float4* wq4 = (const float4*)(dsp_s + c * IC);
      float ax = 0.f, ay = 0.f;
#pragma unroll
      for (int ib = 0; ib < IC / 16; ++ib) {
        float2 f[16];
        float4 g0 = wq4[4 * ib + 0];
        float4 g1 = wq4[4 * ib + 1];
        float4 g2 = wq4[4 * ib + 2];
        float4 g3 = wq4[4 * ib + 3];
#pragma unroll
        for (int u = 0; u < 16; ++u) f[u] = hp[(16 * ib + u) * (ROWP / 2)];
        ax += f[0].x * g0.x + f[1].x * g0.y + f[2].x * g0.z + f[3].x * g0.w;
        ay += f[0].y * g0.x + f[1].y * g0.y + f[2].y * g0.z + f[3].y * g0.w;
        ax += f[4].x * g1.x + f[5].x * g1.y + f[6].x * g1.z + f[7].x * g1.w;
        ay += f[4].y * g1.x + f[5].y * g1.y + f[6].y * g1.z + f[7].y * g1.w;
        ax += f[8].x * g2.x + f[9].x * g2.y + f[10].x * g2.z + f[11].x * g2.w;
        ay += f[8].y * g2.x + f[9].y * g2.y + f[10].y * g2.z + f[11].y * g2.w;
        ax += f[12].x * g3.x + f[13].x * g3.y + f[14].x * g3.z + f[15].x * g3.w;
        ay += f[12].y * g3.x + f[13].y * g3.y + f[14].y * g3.z + f[15].y * g3.w;
      }
      hv[c * DP + 2 * d2] = ax;
      hv[c * DP + 2 * d2 + 1] = ay;
    }
    __syncthreads();

    // ---- phase S: squash + next tq + next norms (warps 0..4) ----
    if (w < NC) {
      const int c = w;
      const float* hvc = hv + c * DP;
      float s2 = 0.f;
      for (int d = lane; d < DD; d += 32) {
        float x = hvc[d];
        s2 += x * x;
      }
      s2 = warp_sum(s2);
      float sc = s2 / ((1.f + s2) * sqrtf(s2 + EPSF));
      if (r < 2) {
        float2* tvc = tv + c * DP;
        float s = 0.f, sq = 0.f;
        for (int d = lane; d < DD; d += 32) {
          float vd = hvc[d] * sc;
          float x = (tvc[d].x + vd) * 0.5f;
          tvc[d] = make_float2(x, vd);
          s += x;
          sq += x * x;
        }
        s = warp_sum(s);
        sq = warp_sum(sq);
        if (lane == 0) {
          float mean = s * (1.f / DD);
          rnq[c] = sqrtf(fmaxf(sq - DD * mean * mean, 0.f));
          stq[c] = s;
        }
      } else {
        for (int d = lane; d < DD; d += 32)
          out[q * CD + c * DD + d] = hvc[d] * sc;
      }
    }
    __syncthreads();
  }
}

// ---------------------------------------------------------------------------
extern "C" void kernel_launch(void* const* d_in, const int* in_sizes, int n_in,
                              void* d_out, int out_size) {
  const float *m = nullptr, *q = nullptr, *W = nullptr, *b = nullptr;
  for (int i = 0; i < n_in; ++i) {
    switch (in_sizes[i]) {
      case IC * KD: m = (const float*)d_in[i]; break;
      case NQV * KD: q = (const float*)d_in[i]; break;
      case KD * CD: W = (const float*)d_in[i]; break;
      case CD: b = (const float*)d_in[i]; break;
      default: break;
    }
  }
  float* out = (float*)d_out;

  void *p_hm, *p_hq, *p_hmT, *p_hmP, *p_mean, *p_norm, *p_wp;
  cudaGetSymbolAddress(&p_hm, g_hm);
  cudaGetSymbolAddress(&p_hq, g_hq);
  cudaGetSymbolAddress(&p_hmT, g_hmT);
  cudaGetSymbolAddress(&p_hmP, g_hmP);
  cudaGetSymbolAddress(&p_mean, g_mean);
  cudaGetSymbolAddress(&p_norm, g_norm);
  cudaGetSymbolAddress(&p_wp, g_Wp);

  static bool attr_set = false;
  if (!attr_set) {
    cudaFuncSetAttribute(routing_kernel,
                         cudaFuncAttributeMaxDynamicSharedMemorySize,
                         SMF_TOTAL * 4);
    attr_set = true;
  }

  wpad_kernel<<<(KD * CDP / 4 + 255) / 256, 256>>>(W, (float*)p_wp);

  dim3 gg(CDP / BN, (IC + NQV) / BM);  // (24, 12) = 288 blocks
  gemm_kernel<<<gg, 128>>>(m, q, (const float*)p_wp, b, (float*)p_hm,
                           (float*)p_hq);

  prep_kernel<<<180, 256>>>((const float*)p_hm, (float*)p_hmP, (float*)p_hmT,
                            (float*)p_mean, (float*)p_norm);

  routing_kernel<<<NQV, 512, SMF_TOTAL * 4>>>(
      (const float*)p_hmT, (const float*)p_hmP, (const float*)p_mean,
      (const float*)p_norm, (const float*)p_hq, out);
}